// round 1
// baseline (speedup 1.0000x reference)
#include <cuda_runtime.h>
#include <cuda_bf16.h>

// Problem: B=8, T=128, D=256
//   E[b,t,p,q]   = exp(dec[b,p] * enc[b,t,q])
//   colsum[b,t,q] = sum_p E      (function of x_q = enc[b,t,q])
//   rowsum[b,t,q] = sum_r exp(dec[b,q] * enc[b,t,r])
//   out[b,q]     = sum_t enc[b,t,q] * colsum / rowsum
//
// One CTA per (b,t). Thread q accumulates both sums over k.
// MUFU(EX2)-bound: 2*B*T*D^2 = 134M exps.

#define B_DIM 8
#define T_DIM 128
#define D_DIM 256

__device__ __forceinline__ float ex2f(float x) {
    float y;
    asm("ex2.approx.ftz.f32 %0, %1;" : "=f"(y) : "f"(x));
    return y;
}

__global__ void zero_out_kernel(float* __restrict__ out, int n) {
    int i = blockIdx.x * blockDim.x + threadIdx.x;
    if (i < n) out[i] = 0.0f;
}

__global__ __launch_bounds__(D_DIM) void attn_ctx_kernel(
    const float* __restrict__ dec,   // [B, D]
    const float* __restrict__ enc,   // [B, T, D]
    float* __restrict__ out)         // [B, D]
{
    const int t = blockIdx.x;
    const int b = blockIdx.y;
    const int q = threadIdx.x;

    __shared__ float sdec[D_DIM];  // dec * log2(e)
    __shared__ float senc[D_DIM];  // enc row (b, t)

    const float LOG2E = 1.4426950408889634f;

    float xq = enc[(b * T_DIM + t) * D_DIM + q];
    sdec[q] = dec[b * D_DIM + q] * LOG2E;
    senc[q] = xq;
    __syncthreads();

    const float dq2 = sdec[q];            // dec[b,q] * log2e
    const float xq2 = xq;                 // enc[b,t,q]

    float rs = 0.0f;  // rowsum: sum_k exp(dec[b,q] * enc[b,t,k])
    float cs = 0.0f;  // colsum: sum_k exp(dec[b,k] * enc[b,t,q])

    #pragma unroll 16
    for (int k = 0; k < D_DIM; ++k) {
        float xk = senc[k];   // broadcast LDS, conflict-free
        float dk = sdec[k];   // broadcast LDS, conflict-free
        rs += ex2f(dq2 * xk);
        cs += ex2f(dk * xq2);
    }

    // contribution of timestep t to out[b,q]
    atomicAdd(&out[b * D_DIM + q], xq2 * cs / rs);
}

extern "C" void kernel_launch(void* const* d_in, const int* in_sizes, int n_in,
                              void* d_out, int out_size) {
    const float* dec = (const float*)d_in[0];   // [8, 256]
    const float* enc = (const float*)d_in[1];   // [8, 128, 256]
    float* out = (float*)d_out;                 // [8, 256] = 2048 floats

    zero_out_kernel<<<(out_size + 255) / 256, 256>>>(out, out_size);

    dim3 grid(T_DIM, B_DIM);
    attn_ctx_kernel<<<grid, D_DIM>>>(dec, enc, out);
}